// round 1
// baseline (speedup 1.0000x reference)
#include <cuda_runtime.h>

#define NB 16
#define NC 64
#define NH 128
#define NW 128
#define NPIX (NH*NW)
#define TW 32

// 67 MB scratch for the summed depthwise field T (device global: no allocation)
__device__ float g_T[(size_t)NB * NC * NH * NW];

// ---------------------------------------------------------------------------
// Kernel A: per (batch, channel), column strip of 32 output cols x 128 rows.
//   phase 1: load x tile (cols c0-11 .. c0+42) into smem (zero OOB cols)
//   phase 2: y = x + avgpool3(x) + maxpool3(x)   (cols c0-10 .. c0+41)
//   phase 3: horizontal convs H7/H11/H21 of y (biases x3) for the 32 out cols
//   phase 4: vertical convs V7/V11/V21 + direct 5x5 of y (biases x3) -> T
// Full-height tiles => no vertical recompute for the V pass.
// ---------------------------------------------------------------------------
__global__ __launch_bounds__(256, 2) void msca_dw_kernel(
    const float* __restrict__ x,
    const float* __restrict__ w55,    const float* __restrict__ b55,
    const float* __restrict__ w17_0,  const float* __restrict__ b17_0,
    const float* __restrict__ w17_1,  const float* __restrict__ b17_1,
    const float* __restrict__ w111_0, const float* __restrict__ b111_0,
    const float* __restrict__ w111_1, const float* __restrict__ b111_1,
    const float* __restrict__ w211_0, const float* __restrict__ b211_0,
    const float* __restrict__ w211_1, const float* __restrict__ b211_1)
{
    extern __shared__ float sm[];
    float* sy = sm;              // [128][52]  y cols c0-10 .. c0+41
    float* su = sm + 128 * 52;   // union: sx[128][54] (phases 1-2), sh[3][128*32] (phases 3-4)

    const int c0  = blockIdx.x * TW;
    const int c   = blockIdx.y;
    const int b   = blockIdx.z;
    const int tid = threadIdx.x;

    const float* xp = x + (size_t)(b * NC + c) * NPIX;

    // ---- phase 1: load x (cols c0-11 .. c0+42, zero outside image) ----
    for (int idx = tid; idx < 128 * 54; idx += 256) {
        const int r = idx / 54, j = idx - r * 54;
        const int gc = c0 - 11 + j;
        su[idx] = ((unsigned)gc < NW) ? xp[r * NW + gc] : 0.f;
    }
    __syncthreads();

    // ---- phase 2: y = x + avg3(x) + max3(x) ----
    // avg: count_include_pad (sum of valid taps / 9, OOB stored as 0 => just sum/9)
    // max: padding is -inf => max over valid taps only (guard needed)
    for (int idx = tid; idx < 128 * 52; idx += 256) {
        const int r = idx / 52, j = idx - r * 52;
        const int gc = c0 - 10 + j;
        float yv = 0.f;
        if ((unsigned)gc < NW) {
            const int sj = j + 1;                 // col in sx frame (offset -11 vs -10)
            const float cen = su[r * 54 + sj];
            float s = 0.f, m = -3.402823466e38f;
            #pragma unroll
            for (int dr = -1; dr <= 1; dr++) {
                const int rr = r + dr;
                if ((unsigned)rr < NH) {
                    #pragma unroll
                    for (int dc = -1; dc <= 1; dc++) {
                        const float v = su[rr * 54 + sj + dc];
                        s += v;                   // OOB cols are 0 in smem: correct for avg
                        const int cc = gc + dc;
                        if ((unsigned)cc < NW) m = fmaxf(m, v);
                    }
                }
            }
            yv = cen + s * (1.f / 9.f) + m;
        }
        sy[idx] = yv;
    }
    __syncthreads();

    // ---- phase 3: horizontal convs (overwrite sx region with sh) ----
    float wh7[7], wh11[11], wh21[21];
    #pragma unroll
    for (int i = 0; i < 7;  i++) wh7[i]  = w17_0[c * 7 + i];
    #pragma unroll
    for (int i = 0; i < 11; i++) wh11[i] = w111_0[c * 11 + i];
    #pragma unroll
    for (int i = 0; i < 21; i++) wh21[i] = w211_0[c * 21 + i];
    const float bh7  = 3.f * b17_0[c];
    const float bh11 = 3.f * b111_0[c];
    const float bh21 = 3.f * b211_0[c];

    for (int idx = tid; idx < 128 * 32; idx += 256) {
        const int r = idx >> 5, oc = idx & 31;
        const float* yr = sy + r * 52 + oc;       // y col (c0+oc-10) at offset 0
        float a7 = bh7, a11 = bh11, a21 = bh21;
        #pragma unroll
        for (int i = 0; i < 21; i++) a21 += wh21[i] * yr[i];
        #pragma unroll
        for (int i = 0; i < 11; i++) a11 += wh11[i] * yr[5 + i];
        #pragma unroll
        for (int i = 0; i < 7;  i++) a7  += wh7[i]  * yr[7 + i];
        su[idx]        = a7;
        su[4096 + idx] = a11;
        su[8192 + idx] = a21;
    }
    __syncthreads();

    // ---- phase 4: 5x5 direct + vertical convs, write T ----
    float w5[25];
    #pragma unroll
    for (int i = 0; i < 25; i++) w5[i] = w55[c * 25 + i];
    float wv7[7], wv11[11], wv21[21];
    #pragma unroll
    for (int i = 0; i < 7;  i++) wv7[i]  = w17_1[c * 7 + i];
    #pragma unroll
    for (int i = 0; i < 11; i++) wv11[i] = w111_1[c * 11 + i];
    #pragma unroll
    for (int i = 0; i < 21; i++) wv21[i] = w211_1[c * 21 + i];
    const float tb = 3.f * (b55[c] + b17_1[c] + b111_1[c] + b211_1[c]);

    float* Tp = g_T + (size_t)(b * NC + c) * NPIX + c0;

    for (int idx = tid; idx < 128 * 32; idx += 256) {
        const int r = idx >> 5, oc = idx & 31;
        float acc = tb;
        // 5x5 on y (col offset: j = oc+10+dc, dc in [-2,2] => base oc+8)
        #pragma unroll
        for (int dr = -2; dr <= 2; dr++) {
            const int rr = r + dr;
            if ((unsigned)rr < NH) {
                const float* yr = sy + rr * 52 + oc + 8;
                #pragma unroll
                for (int i = 0; i < 5; i++) acc += w5[(dr + 2) * 5 + i] * yr[i];
            }
        }
        // vertical convs on H fields (one guarded row loop for all three)
        #pragma unroll
        for (int dr = -10; dr <= 10; dr++) {
            const int rr = r + dr;
            if ((unsigned)rr < NH) {
                const int hidx = rr * 32 + oc;
                acc += wv21[dr + 10] * su[8192 + hidx];
                if (dr >= -5 && dr <= 5) acc += wv11[dr + 5] * su[4096 + hidx];
                if (dr >= -3 && dr <= 3) acc += wv7[dr + 3]  * su[hidx];
            }
        }
        Tp[r * NW + oc] = acc;
    }
}

// ---------------------------------------------------------------------------
// Kernel B: out = (W[64x64] @ T + 3*b11) * x
// Block: 64 out-channels x 128 pixels. Thread: 8 och x 4 pix register tile.
// ---------------------------------------------------------------------------
__global__ __launch_bounds__(256) void msca_pw_kernel(
    const float* __restrict__ x,
    const float* __restrict__ w11, const float* __restrict__ b11,
    float* __restrict__ out)
{
    extern __shared__ float sm[];
    float* sT = sm;               // [64][128]
    float* sW = sm + 64 * 128;    // [64][64]
    float* sB = sW + 64 * 64;     // [64]

    const int b   = blockIdx.y;
    const int p0  = blockIdx.x * 128;
    const int tid = threadIdx.x;

    const float* Tb = g_T + (size_t)b * (NC * NPIX) + p0;
    for (int idx = tid; idx < 64 * 128; idx += 256) {
        const int k = idx >> 7, j = idx & 127;
        sT[idx] = Tb[(size_t)k * NPIX + j];
    }
    for (int idx = tid; idx < 64 * 64; idx += 256) sW[idx] = w11[idx];
    if (tid < 64) sB[tid] = 3.f * b11[tid];
    __syncthreads();

    const int pg = tid & 31;   // pixels pg*4 .. pg*4+3
    const int og = tid >> 5;   // out-ch og*8 .. og*8+7

    float acc[8][4];
    #pragma unroll
    for (int i = 0; i < 8; i++)
        #pragma unroll
        for (int j = 0; j < 4; j++) acc[i][j] = 0.f;

    #pragma unroll 4
    for (int k = 0; k < 64; k++) {
        const float4 t4 = *(const float4*)&sT[k * 128 + pg * 4];
        #pragma unroll
        for (int i = 0; i < 8; i++) {
            const float wv = sW[(og * 8 + i) * 64 + k];  // warp-uniform broadcast
            acc[i][0] += wv * t4.x;
            acc[i][1] += wv * t4.y;
            acc[i][2] += wv * t4.z;
            acc[i][3] += wv * t4.w;
        }
    }

    const float* xb = x + (size_t)b * (NC * NPIX) + p0;
    float*       ob = out + (size_t)b * (NC * NPIX) + p0;
    #pragma unroll
    for (int i = 0; i < 8; i++) {
        const int o = og * 8 + i;
        const float bias = sB[o];
        const float4 x4 = *(const float4*)&xb[(size_t)o * NPIX + pg * 4];
        float4 r;
        r.x = (acc[i][0] + bias) * x4.x;
        r.y = (acc[i][1] + bias) * x4.y;
        r.z = (acc[i][2] + bias) * x4.z;
        r.w = (acc[i][3] + bias) * x4.w;
        *(float4*)&ob[(size_t)o * NPIX + pg * 4] = r;
    }
}

// ---------------------------------------------------------------------------
extern "C" void kernel_launch(void* const* d_in, const int* in_sizes, int n_in,
                              void* d_out, int out_size)
{
    const float* x      = (const float*)d_in[0];
    const float* w55    = (const float*)d_in[1];
    const float* b55    = (const float*)d_in[2];
    const float* w17_0  = (const float*)d_in[3];
    const float* b17_0  = (const float*)d_in[4];
    const float* w17_1  = (const float*)d_in[5];
    const float* b17_1  = (const float*)d_in[6];
    const float* w111_0 = (const float*)d_in[7];
    const float* b111_0 = (const float*)d_in[8];
    const float* w111_1 = (const float*)d_in[9];
    const float* b111_1 = (const float*)d_in[10];
    const float* w211_0 = (const float*)d_in[11];
    const float* b211_0 = (const float*)d_in[12];
    const float* w211_1 = (const float*)d_in[13];
    const float* b211_1 = (const float*)d_in[14];
    const float* w11    = (const float*)d_in[15];
    const float* b11    = (const float*)d_in[16];
    float* out = (float*)d_out;

    const int smemA = (128 * 52 + 3 * 128 * 32) * sizeof(float); // 75776 B (union covers sx)
    const int smemB = (64 * 128 + 64 * 64 + 64) * sizeof(float); // 49408 B

    // idempotent, not a stream op: safe under graph capture
    cudaFuncSetAttribute(msca_dw_kernel, cudaFuncAttributeMaxDynamicSharedMemorySize, smemA);
    cudaFuncSetAttribute(msca_pw_kernel, cudaFuncAttributeMaxDynamicSharedMemorySize, smemB);

    dim3 gA(NW / TW, NC, NB);
    msca_dw_kernel<<<gA, 256, smemA>>>(x,
        w55, b55, w17_0, b17_0, w17_1, b17_1,
        w111_0, b111_0, w111_1, b111_1,
        w211_0, b211_0, w211_1, b211_1);

    dim3 gB(NPIX / 128, NB);
    msca_pw_kernel<<<gB, 256, smemB>>>(x, w11, b11, out);
}

// round 2
// speedup vs baseline: 1.4053x; 1.4053x over previous
#include <cuda_runtime.h>

#define NB 16
#define NC 64
#define NH 128
#define NW 128
#define NPIX (NH*NW)
#define TW 32

// 67 MB scratch for the summed depthwise field T (device global: no allocation)
__device__ float g_T[(size_t)NB * NC * NH * NW];

// smem layout (floats):
//   SY  at 0      : [132][52]  y, rows 0,1,130,131 zero (image row = i-2)
//   SX  at 6864   : [130][54]  x tile, rows 1..128 used (image row = i-1)
//   HS  at 13884  : [130][52]  horiz sum3, rows 0 & 129 zero
//   HM  at 20644  : [130][52]  horiz max3 (rows clamped at use)
//   SH21 at 6864, SH11 at 11600, SH7 at 16336 : [148][32] each, rows 0..9 &
//       138..147 zero (overlaps dead SX after phase 2b)
#define OF_SY   0
#define OF_SX   6864
#define OF_HS   13884
#define OF_HM   20644
#define OF_SH   6864
#define SH_FSZ  4736      // 148*32
#define SMEM_A_FLOATS 27404

__global__ __launch_bounds__(256, 2) void msca_dw_kernel(
    const float* __restrict__ x,
    const float* __restrict__ w55,    const float* __restrict__ b55,
    const float* __restrict__ w17_0,  const float* __restrict__ b17_0,
    const float* __restrict__ w17_1,  const float* __restrict__ b17_1,
    const float* __restrict__ w111_0, const float* __restrict__ b111_0,
    const float* __restrict__ w111_1, const float* __restrict__ b111_1,
    const float* __restrict__ w211_0, const float* __restrict__ b211_0,
    const float* __restrict__ w211_1, const float* __restrict__ b211_1)
{
    extern __shared__ float sm[];
    float* sy = sm + OF_SY;
    float* sx = sm + OF_SX;
    float* hs = sm + OF_HS;
    float* hm = sm + OF_HM;

    const int c0  = blockIdx.x * TW;
    const int c   = blockIdx.y;
    const int b   = blockIdx.z;
    const int tid = threadIdx.x;
    const bool interior = (c0 >= 11 && c0 + 42 <= 127);   // cols never OOB

    const float* xp = x + (size_t)(b * NC + c) * NPIX;

    // ---- phase 1: zero halos + load x tile (rows 1..128, cols c0-11..c0+42) ----
    for (int idx = tid; idx < 208; idx += 256) {           // sy rows 0,1,130,131
        const int h = idx / 52, j = idx - h * 52;
        const int row = (h < 2) ? h : 128 + h;
        sy[row * 52 + j] = 0.f;
    }
    for (int idx = tid; idx < 104; idx += 256) {           // hs rows 0,129
        const int h = idx / 52, j = idx - h * 52;
        hs[((h == 0) ? 0 : 129) * 52 + j] = 0.f;
    }
    if (interior) {
        for (int idx = tid; idx < 128 * 54; idx += 256) {
            const int r = idx / 54, j = idx - r * 54;
            sx[(r + 1) * 54 + j] = xp[r * NW + (c0 - 11 + j)];
        }
    } else {
        for (int idx = tid; idx < 128 * 54; idx += 256) {
            const int r = idx / 54, j = idx - r * 54;
            const int gc = c0 - 11 + j;
            sx[(r + 1) * 54 + j] = ((unsigned)gc < NW) ? xp[r * NW + gc] : 0.f;
        }
    }
    __syncthreads();

    // ---- phase 2a: horizontal sum3 / max3 ----
    // hs col j <-> gc = c0-10+j; window = sx cols j..j+2 (row r+1).
    if (interior) {
        for (int idx = tid; idx < 128 * 52; idx += 256) {
            const int r = idx / 52, j = idx - r * 52;
            const float* xr = sx + (r + 1) * 54 + j;
            const float v0 = xr[0], v1 = xr[1], v2 = xr[2];
            hs[(r + 1) * 52 + j] = v0 + v1 + v2;
            hm[(r + 1) * 52 + j] = fmaxf(fmaxf(v0, v1), v2);
        }
    } else {
        const int s_lo = (11 - c0 > 0) ? 11 - c0 : 0;      // clamp to valid gc
        const int s_hi = (138 - c0 < 53) ? 138 - c0 : 53;
        for (int idx = tid; idx < 128 * 52; idx += 256) {
            const int r = idx / 52, j = idx - r * 52;
            const float* xr = sx + (r + 1) * 54;
            hs[(r + 1) * 52 + j] = xr[j] + xr[j + 1] + xr[j + 2];
            const int a = min(max(j,     s_lo), s_hi);
            const int d = min(max(j + 1, s_lo), s_hi);
            const int e = min(max(j + 2, s_lo), s_hi);
            hm[(r + 1) * 52 + j] = fmaxf(fmaxf(xr[a], xr[d]), xr[e]);
        }
    }
    __syncthreads();

    // ---- phase 2b: y = x + sum3x3/9 + max3x3 -> sy (rows +2) ----
    {
        const int jv_lo = 10 - c0, jv_hi = 137 - c0;
        for (int idx = tid; idx < 128 * 52; idx += 256) {
            const int r = idx / 52, j = idx - r * 52;
            const float s = hs[r * 52 + j] + hs[(r + 1) * 52 + j] + hs[(r + 2) * 52 + j];
            const int rlo = (r == 0)   ? 1   : r;        // clamp rows for max
            const int rhi = (r == 127) ? 128 : r + 2;
            const float m = fmaxf(hm[rlo * 52 + j],
                            fmaxf(hm[(r + 1) * 52 + j], hm[rhi * 52 + j]));
            const float cen = sx[(r + 1) * 54 + j + 1];
            float yv = cen + s * (1.f / 9.f) + m;
            if (!interior && (j < jv_lo || j > jv_hi)) yv = 0.f;
            sy[(r + 2) * 52 + j] = yv;
        }
    }
    __syncthreads();

    // ---- phase 3: horizontal convs -> padded sh fields (4 cols/thread) ----
    float* sh21 = sm + OF_SH;
    float* sh11 = sh21 + SH_FSZ;
    float* sh7  = sh11 + SH_FSZ;

    // zero sh halo rows 0..9 / 138..147 (region = dead sx; disjoint from writes below)
    for (int idx = tid; idx < 1920; idx += 256) {
        const int f = idx / 640, rest = idx - f * 640;
        const int h = rest >> 5, col = rest & 31;
        const int row = (h < 10) ? h : 128 + h;
        (sm + OF_SH + f * SH_FSZ)[row * 32 + col] = 0.f;
    }

    float wh7[7], wh11[11], wh21[21];
    #pragma unroll
    for (int i = 0; i < 7;  i++) wh7[i]  = w17_0[c * 7 + i];
    #pragma unroll
    for (int i = 0; i < 11; i++) wh11[i] = w111_0[c * 11 + i];
    #pragma unroll
    for (int i = 0; i < 21; i++) wh21[i] = w211_0[c * 21 + i];
    const float bh7  = 3.f * b17_0[c];
    const float bh11 = 3.f * b111_0[c];
    const float bh21 = 3.f * b211_0[c];

    #pragma unroll
    for (int k = 0; k < 4; k++) {
        const int it = tid + k * 256;          // 1024 items: 128 rows x 8 col-groups
        const int r = it >> 3, oc4 = (it & 7) * 4;
        const float* yr = sy + (r + 2) * 52 + oc4;   // 16B-aligned
        float win[24];
        #pragma unroll
        for (int q = 0; q < 6; q++) {
            const float4 t4 = *(const float4*)(yr + 4 * q);
            win[4*q] = t4.x; win[4*q+1] = t4.y; win[4*q+2] = t4.z; win[4*q+3] = t4.w;
        }
        float a21[4] = {bh21, bh21, bh21, bh21};
        float a11[4] = {bh11, bh11, bh11, bh11};
        float a7 [4] = {bh7,  bh7,  bh7,  bh7 };
        #pragma unroll
        for (int i = 0; i < 21; i++)
            #pragma unroll
            for (int t = 0; t < 4; t++) a21[t] += wh21[i] * win[i + t];
        #pragma unroll
        for (int i = 0; i < 11; i++)
            #pragma unroll
            for (int t = 0; t < 4; t++) a11[t] += wh11[i] * win[5 + i + t];
        #pragma unroll
        for (int i = 0; i < 7; i++)
            #pragma unroll
            for (int t = 0; t < 4; t++) a7[t] += wh7[i] * win[7 + i + t];
        const int so = (r + 10) * 32 + oc4;
        *(float4*)(sh21 + so) = make_float4(a21[0], a21[1], a21[2], a21[3]);
        *(float4*)(sh11 + so) = make_float4(a11[0], a11[1], a11[2], a11[3]);
        *(float4*)(sh7  + so) = make_float4(a7[0],  a7[1],  a7[2],  a7[3]);
    }
    __syncthreads();

    // ---- phase 4: 5x5 direct + vertical convs (4 rows/thread), branch-free ----
    float w5[25];
    #pragma unroll
    for (int i = 0; i < 25; i++) w5[i] = w55[c * 25 + i];
    float wv7[7], wv11[11], wv21[21];
    #pragma unroll
    for (int i = 0; i < 7;  i++) wv7[i]  = w17_1[c * 7 + i];
    #pragma unroll
    for (int i = 0; i < 11; i++) wv11[i] = w111_1[c * 11 + i];
    #pragma unroll
    for (int i = 0; i < 21; i++) wv21[i] = w211_1[c * 21 + i];
    const float tb = 3.f * (b55[c] + b17_1[c] + b111_1[c] + b211_1[c]);

    float* Tp = g_T + (size_t)(b * NC + c) * NPIX + c0;

    #pragma unroll
    for (int k = 0; k < 4; k++) {
        const int it = tid + k * 256;          // 1024 items: 32 row-groups x 32 cols
        const int oc = it & 31, r4 = (it >> 5) * 4;
        float acc[4] = {tb, tb, tb, tb};

        // 5x5 on y: padded sy rows r4..r4+7, cols oc+8..oc+12
        #pragma unroll
        for (int rr = 0; rr < 8; rr++) {
            const float* yp = sy + (r4 + rr) * 52 + oc + 8;
            const float y0 = yp[0], y1 = yp[1], y2 = yp[2], y3 = yp[3], y4 = yp[4];
            #pragma unroll
            for (int t = 0; t < 4; t++) {
                const int kk = rr - t;
                if (kk >= 0 && kk <= 4) {
                    acc[t] += w5[kk*5+0]*y0 + w5[kk*5+1]*y1 + w5[kk*5+2]*y2
                            + w5[kk*5+3]*y3 + w5[kk*5+4]*y4;
                }
            }
        }
        // vertical 21 over sh21 rows r4..r4+23
        {
            const float* p = sh21 + r4 * 32 + oc;
            #pragma unroll
            for (int i = 0; i < 24; i++) {
                const float v = p[i * 32];
                #pragma unroll
                for (int t = 0; t < 4; t++) {
                    const int kk = i - t;
                    if (kk >= 0 && kk <= 20) acc[t] += wv21[kk] * v;
                }
            }
        }
        // vertical 11 over sh11 rows r4+5..r4+18
        {
            const float* p = sh11 + (r4 + 5) * 32 + oc;
            #pragma unroll
            for (int i = 0; i < 14; i++) {
                const float v = p[i * 32];
                #pragma unroll
                for (int t = 0; t < 4; t++) {
                    const int kk = i - t;
                    if (kk >= 0 && kk <= 10) acc[t] += wv11[kk] * v;
                }
            }
        }
        // vertical 7 over sh7 rows r4+7..r4+16
        {
            const float* p = sh7 + (r4 + 7) * 32 + oc;
            #pragma unroll
            for (int i = 0; i < 10; i++) {
                const float v = p[i * 32];
                #pragma unroll
                for (int t = 0; t < 4; t++) {
                    const int kk = i - t;
                    if (kk >= 0 && kk <= 6) acc[t] += wv7[kk] * v;
                }
            }
        }
        #pragma unroll
        for (int t = 0; t < 4; t++) Tp[(r4 + t) * NW + oc] = acc[t];
    }
}

// ---------------------------------------------------------------------------
// Kernel B: out = (W[64x64] @ T + 3*b11) * x
// Block: 64 out-channels x 128 pixels. Thread: 8 och x 4 pix register tile.
// ---------------------------------------------------------------------------
__global__ __launch_bounds__(256, 4) void msca_pw_kernel(
    const float* __restrict__ x,
    const float* __restrict__ w11, const float* __restrict__ b11,
    float* __restrict__ out)
{
    extern __shared__ float sm[];
    float* sT = sm;               // [64][128]
    float* sW = sm + 64 * 128;    // [64][64]
    float* sB = sW + 64 * 64;     // [64]

    const int b   = blockIdx.y;
    const int p0  = blockIdx.x * 128;
    const int tid = threadIdx.x;

    const float* Tb = g_T + (size_t)b * (NC * NPIX) + p0;
    // staged with float4 for MLP
    #pragma unroll
    for (int k = 0; k < 8; k++) {
        const int idx = tid + k * 256;            // 2048 float4s
        const int row = idx >> 5, j4 = idx & 31;
        ((float4*)sT)[idx] = *(const float4*)(Tb + (size_t)row * NPIX + j4 * 4);
    }
    #pragma unroll
    for (int k = 0; k < 4; k++)
        ((float4*)sW)[tid + k * 256] = ((const float4*)w11)[tid + k * 256];
    if (tid < 64) sB[tid] = 3.f * b11[tid];
    __syncthreads();

    const int pg = tid & 31;   // pixels pg*4 .. pg*4+3
    const int og = tid >> 5;   // out-ch og*8 .. og*8+7

    float acc[8][4];
    #pragma unroll
    for (int i = 0; i < 8; i++)
        #pragma unroll
        for (int j = 0; j < 4; j++) acc[i][j] = 0.f;

    #pragma unroll 8
    for (int k = 0; k < 64; k++) {
        const float4 t4 = *(const float4*)&sT[k * 128 + pg * 4];
        #pragma unroll
        for (int i = 0; i < 8; i++) {
            const float wv = sW[(og * 8 + i) * 64 + k];  // warp-uniform broadcast
            acc[i][0] += wv * t4.x;
            acc[i][1] += wv * t4.y;
            acc[i][2] += wv * t4.z;
            acc[i][3] += wv * t4.w;
        }
    }

    const float* xb = x + (size_t)b * (NC * NPIX) + p0;
    float*       ob = out + (size_t)b * (NC * NPIX) + p0;
    #pragma unroll
    for (int i = 0; i < 8; i++) {
        const int o = og * 8 + i;
        const float bias = sB[o];
        const float4 x4 = *(const float4*)&xb[(size_t)o * NPIX + pg * 4];
        float4 r;
        r.x = (acc[i][0] + bias) * x4.x;
        r.y = (acc[i][1] + bias) * x4.y;
        r.z = (acc[i][2] + bias) * x4.z;
        r.w = (acc[i][3] + bias) * x4.w;
        *(float4*)&ob[(size_t)o * NPIX + pg * 4] = r;
    }
}

// ---------------------------------------------------------------------------
extern "C" void kernel_launch(void* const* d_in, const int* in_sizes, int n_in,
                              void* d_out, int out_size)
{
    const float* x      = (const float*)d_in[0];
    const float* w55    = (const float*)d_in[1];
    const float* b55    = (const float*)d_in[2];
    const float* w17_0  = (const float*)d_in[3];
    const float* b17_0  = (const float*)d_in[4];
    const float* w17_1  = (const float*)d_in[5];
    const float* b17_1  = (const float*)d_in[6];
    const float* w111_0 = (const float*)d_in[7];
    const float* b111_0 = (const float*)d_in[8];
    const float* w111_1 = (const float*)d_in[9];
    const float* b111_1 = (const float*)d_in[10];
    const float* w211_0 = (const float*)d_in[11];
    const float* b211_0 = (const float*)d_in[12];
    const float* w211_1 = (const float*)d_in[13];
    const float* b211_1 = (const float*)d_in[14];
    const float* w11    = (const float*)d_in[15];
    const float* b11    = (const float*)d_in[16];
    float* out = (float*)d_out;

    const int smemA = SMEM_A_FLOATS * sizeof(float);             // 109616 B
    const int smemB = (64 * 128 + 64 * 64 + 64) * sizeof(float); // 49408 B

    cudaFuncSetAttribute(msca_dw_kernel, cudaFuncAttributeMaxDynamicSharedMemorySize, smemA);
    cudaFuncSetAttribute(msca_pw_kernel, cudaFuncAttributeMaxDynamicSharedMemorySize, smemB);

    dim3 gA(NW / TW, NC, NB);
    msca_dw_kernel<<<gA, 256, smemA>>>(x,
        w55, b55, w17_0, b17_0, w17_1, b17_1,
        w111_0, b111_0, w111_1, b111_1,
        w211_0, b211_0, w211_1, b211_1);

    dim3 gB(NPIX / 128, NB);
    msca_pw_kernel<<<gB, 256, smemB>>>(x, w11, b11, out);
}

// round 3
// speedup vs baseline: 1.7171x; 1.2219x over previous
#include <cuda_runtime.h>

#define NB 16
#define NC 64
#define NH 128
#define NW 128
#define NPIX (NH*NW)
#define TW 32

typedef unsigned long long ull;

__device__ float g_T[(size_t)NB * NC * NH * NW];

// ---- packed fp32x2 helpers (exact IEEE fp32 per lane) ----
__device__ __forceinline__ ull fma2(ull a, ull b, ull c) {
    ull d;
    asm("fma.rn.f32x2 %0, %1, %2, %3;" : "=l"(d) : "l"(a), "l"(b), "l"(c));
    return d;
}
__device__ __forceinline__ ull add2(ull a, ull b) {
    ull d; asm("add.rn.f32x2 %0, %1, %2;" : "=l"(d) : "l"(a), "l"(b)); return d;
}
__device__ __forceinline__ ull mul2(ull a, ull b) {
    ull d; asm("mul.rn.f32x2 %0, %1, %2;" : "=l"(d) : "l"(a), "l"(b)); return d;
}
__device__ __forceinline__ ull pack2(float lo, float hi) {
    ull d; asm("mov.b64 %0, {%1, %2};" : "=l"(d) : "f"(lo), "f"(hi)); return d;
}
__device__ __forceinline__ float2 unpack2(ull v) {
    float2 f; asm("mov.b64 {%0, %1}, %2;" : "=f"(f.x), "=f"(f.y) : "l"(v)); return f;
}

// smem layout (floats):
//   SY at 0      : [132][52] y (rows 0,1,130,131 zero; image row = i-2)
//   SX at 6864   : [130][54] x tile (rows 1..128)
//   HS at 13884  : [130][52] horiz sum3 (rows 0,129 zero)
//   HM at 20644  : [130][52] horiz max3
//   SH21/SH11/SH7 at 6864 + f*4736 : [148][32], rows 0..9 & 138..147 zero
//   WD at 27404  : 39 float2 dup'd vertical weights (21 + 11 + 7)
#define OF_SY   0
#define OF_SX   6864
#define OF_HS   13884
#define OF_HM   20644
#define OF_SH   6864
#define SH_FSZ  4736
#define OF_WD   27404
#define SMEM_A_FLOATS (27404 + 78)

__global__ __launch_bounds__(256, 2) void msca_dw_kernel(
    const float* __restrict__ x,
    const float* __restrict__ w55,    const float* __restrict__ b55,
    const float* __restrict__ w17_0,  const float* __restrict__ b17_0,
    const float* __restrict__ w17_1,  const float* __restrict__ b17_1,
    const float* __restrict__ w111_0, const float* __restrict__ b111_0,
    const float* __restrict__ w111_1, const float* __restrict__ b111_1,
    const float* __restrict__ w211_0, const float* __restrict__ b211_0,
    const float* __restrict__ w211_1, const float* __restrict__ b211_1)
{
    extern __shared__ float sm[];
    float* sy = sm + OF_SY;
    float* sx = sm + OF_SX;
    float* hs = sm + OF_HS;
    float* hm = sm + OF_HM;

    const int c0  = blockIdx.x * TW;
    const int c   = blockIdx.y;
    const int b   = blockIdx.z;
    const int tid = threadIdx.x;
    const bool interior = (c0 >= 11 && c0 + 42 <= 127);

    const float* xp = x + (size_t)(b * NC + c) * NPIX;

    // ---- phase 1: halo zeroing + dup'd weight tables + x tile load ----
    for (int idx = tid; idx < 208; idx += 256) {           // sy rows 0,1,130,131
        const int h = idx / 52, j = idx - h * 52;
        sy[((h < 2) ? h : 128 + h) * 52 + j] = 0.f;
    }
    for (int idx = tid; idx < 104; idx += 256) {           // hs rows 0,129
        const int h = idx / 52, j = idx - h * 52;
        hs[((h == 0) ? 0 : 129) * 52 + j] = 0.f;
    }
    {   // dup'd vertical weight tables (packed as (w,w))
        float2* wd = (float2*)(sm + OF_WD);
        if (tid < 21)      { float w = w211_1[c * 21 + tid];        wd[tid]      = make_float2(w, w); }
        else if (tid < 32) { float w = w111_1[c * 11 + (tid - 21)]; wd[tid]      = make_float2(w, w); }
        else if (tid < 39) { float w = w17_1 [c * 7  + (tid - 32)]; wd[tid]      = make_float2(w, w); }
    }
    {   // x tile: sx[(ir+1)*54 + j] = x[ir][c0-11+j], division-free indexing
        int j  = tid % 54;
        int go = (tid / 54) * 128 + (c0 - 11) + j;
        int so = 54 + tid;
        if (interior) {
            #pragma unroll
            for (int k = 0; k < 27; k++) {
                sx[so] = xp[go];
                so += 256; go += 552; j += 40;
                if (j >= 54) { j -= 54; go += 74; }
            }
        } else {
            #pragma unroll
            for (int k = 0; k < 27; k++) {
                const int gc = c0 - 11 + j;
                sx[so] = ((unsigned)gc < NW) ? xp[go] : 0.f;
                so += 256; go += 552; j += 40;
                if (j >= 54) { j -= 54; go += 74; }
            }
        }
    }
    __syncthreads();

    // ---- phase 2a: horizontal sum3 / max3 ----
    {
        int j   = tid % 52;
        int sxo = 54 + tid + 2 * (tid / 52);   // sx[(r+1)*54 + j]
        int ho  = 52 + tid;                    // hs[(r+1)*52 + j]
        if (interior) {
            #pragma unroll
            for (int k = 0; k < 26; k++) {
                const float v0 = sx[sxo], v1 = sx[sxo + 1], v2 = sx[sxo + 2];
                hs[ho] = v0 + v1 + v2;
                hm[ho] = fmaxf(fmaxf(v0, v1), v2);
                ho += 256; sxo += 264; j += 48;
                if (j >= 52) { j -= 52; sxo += 2; }
            }
        } else {
            const int s_lo = (11 - c0 > 0) ? 11 - c0 : 0;
            const int s_hi = (138 - c0 < 53) ? 138 - c0 : 53;
            #pragma unroll
            for (int k = 0; k < 26; k++) {
                hs[ho] = sx[sxo] + sx[sxo + 1] + sx[sxo + 2];
                const int rb = sxo - j;
                const int a = min(max(j,     s_lo), s_hi);
                const int d = min(max(j + 1, s_lo), s_hi);
                const int e = min(max(j + 2, s_lo), s_hi);
                hm[ho] = fmaxf(fmaxf(sx[rb + a], sx[rb + d]), sx[rb + e]);
                ho += 256; sxo += 264; j += 48;
                if (j >= 52) { j -= 52; sxo += 2; }
            }
        }
    }
    __syncthreads();

    // ---- phase 2b: y = x + sum3x3/9 + max3x3 -> sy ----
    {
        const int jv_lo = 10 - c0, jv_hi = 137 - c0;
        int j   = tid % 52;
        int r   = tid / 52;
        int ho  = tid;                          // hs[r*52 + j]
        int sxo = 54 + tid + 2 * r + 1;         // sx[(r+1)*54 + j + 1]
        #pragma unroll
        for (int k = 0; k < 26; k++) {
            const float s = hs[ho] + hs[ho + 52] + hs[ho + 104];
            const int mlo = (r == 0)   ? ho + 52 : ho;
            const int mhi = (r == 127) ? ho + 52 : ho + 104;
            const float m = fmaxf(hm[mlo], fmaxf(hm[ho + 52], hm[mhi]));
            float yv = sx[sxo] + s * (1.f / 9.f) + m;
            if (!interior && (j < jv_lo || j > jv_hi)) yv = 0.f;
            sy[ho + 104] = yv;                  // sy[(r+2)*52 + j]
            ho += 256; sxo += 264; j += 48; r += 4;
            if (j >= 52) { j -= 52; r += 1; sxo += 2; }
        }
    }
    __syncthreads();

    // ---- phase 3: horizontal convs -> padded sh fields (4 cols/thread) ----
    float* sh21 = sm + OF_SH;
    float* sh11 = sh21 + SH_FSZ;
    float* sh7  = sh11 + SH_FSZ;

    for (int idx = tid; idx < 1920; idx += 256) {          // zero sh halo rows
        const int f = idx / 640, rest = idx - f * 640;
        const int h = rest >> 5, col = rest & 31;
        (sm + OF_SH + f * SH_FSZ)[((h < 10) ? h : 128 + h) * 32 + col] = 0.f;
    }

    float wh7[7], wh11[11], wh21[21];
    #pragma unroll
    for (int i = 0; i < 7;  i++) wh7[i]  = w17_0[c * 7 + i];
    #pragma unroll
    for (int i = 0; i < 11; i++) wh11[i] = w111_0[c * 11 + i];
    #pragma unroll
    for (int i = 0; i < 21; i++) wh21[i] = w211_0[c * 21 + i];
    const float bh7  = 3.f * b17_0[c];
    const float bh11 = 3.f * b111_0[c];
    const float bh21 = 3.f * b211_0[c];

    #pragma unroll
    for (int k = 0; k < 4; k++) {
        const int it = tid + k * 256;
        const int r = it >> 3, oc4 = (it & 7) * 4;
        const float* yr = sy + (r + 2) * 52 + oc4;
        float win[24];
        #pragma unroll
        for (int q = 0; q < 6; q++) {
            const float4 t4 = *(const float4*)(yr + 4 * q);
            win[4*q] = t4.x; win[4*q+1] = t4.y; win[4*q+2] = t4.z; win[4*q+3] = t4.w;
        }
        float a21[4] = {bh21, bh21, bh21, bh21};
        float a11[4] = {bh11, bh11, bh11, bh11};
        float a7 [4] = {bh7,  bh7,  bh7,  bh7 };
        #pragma unroll
        for (int i = 0; i < 21; i++)
            #pragma unroll
            for (int t = 0; t < 4; t++) a21[t] += wh21[i] * win[i + t];
        #pragma unroll
        for (int i = 0; i < 11; i++)
            #pragma unroll
            for (int t = 0; t < 4; t++) a11[t] += wh11[i] * win[5 + i + t];
        #pragma unroll
        for (int i = 0; i < 7; i++)
            #pragma unroll
            for (int t = 0; t < 4; t++) a7[t] += wh7[i] * win[7 + i + t];
        const int so = (r + 10) * 32 + oc4;
        *(float4*)(sh21 + so) = make_float4(a21[0], a21[1], a21[2], a21[3]);
        *(float4*)(sh11 + so) = make_float4(a11[0], a11[1], a11[2], a11[3]);
        *(float4*)(sh7  + so) = make_float4(a7[0],  a7[1],  a7[2],  a7[3]);
    }
    __syncthreads();

    // ---- phase 4: scalar 5x5 + packed vertical convs (4 rows x 2 cols/thread item) ----
    float w5[25];
    #pragma unroll
    for (int i = 0; i < 25; i++) w5[i] = w55[c * 25 + i];
    const float tb = 3.f * (b55[c] + b17_1[c] + b111_1[c] + b211_1[c]);
    const ull tbp = pack2(tb, tb);

    const ull* wd21 = (const ull*)(sm + OF_WD);
    const ull* wd11 = wd21 + 21;
    const ull* wd7  = wd21 + 32;

    float* Tp = g_T + (size_t)(b * NC + c) * NPIX + c0;

    #pragma unroll
    for (int k = 0; k < 2; k++) {
        const int it = tid + k * 256;            // 512 items
        const int oc2 = (it & 15) * 2;
        const int r4  = (it >> 4) * 4;

        // scalar 5x5 on y
        float sacc[4][2] = {{0.f,0.f},{0.f,0.f},{0.f,0.f},{0.f,0.f}};
        #pragma unroll
        for (int rr = 0; rr < 8; rr++) {
            const float* yp = sy + (r4 + rr) * 52 + oc2 + 8;
            const float2 q0 = *(const float2*)yp;
            const float2 q1 = *(const float2*)(yp + 2);
            const float2 q2 = *(const float2*)(yp + 4);
            const float y0=q0.x, y1=q0.y, y2=q1.x, y3=q1.y, y4=q2.x, y5=q2.y;
            #pragma unroll
            for (int t = 0; t < 4; t++) {
                const int kk = rr - t;
                if (kk >= 0 && kk <= 4) {
                    const float* wr = w5 + kk * 5;
                    sacc[t][0] += wr[0]*y0 + wr[1]*y1 + wr[2]*y2 + wr[3]*y3 + wr[4]*y4;
                    sacc[t][1] += wr[0]*y1 + wr[1]*y2 + wr[2]*y3 + wr[3]*y4 + wr[4]*y5;
                }
            }
        }

        // packed vertical convs
        ull vacc[4] = {tbp, tbp, tbp, tbp};
        {   // v21: sh21 rows r4 .. r4+23
            const float* base = sh21 + r4 * 32 + oc2;
            ull w0=0, w1=0, w2=0, w3=0;
            #pragma unroll
            for (int i = 0; i < 24; i++) {
                w3 = w2; w2 = w1; w1 = w0;
                if (i <= 20) w0 = wd21[i];
                const ull v = *(const ull*)(base + i * 32);
                if (i <= 20)           vacc[0] = fma2(w0, v, vacc[0]);
                if (i >= 1 && i <= 21) vacc[1] = fma2(w1, v, vacc[1]);
                if (i >= 2 && i <= 22) vacc[2] = fma2(w2, v, vacc[2]);
                if (i >= 3)            vacc[3] = fma2(w3, v, vacc[3]);
            }
        }
        {   // v11: sh11 rows r4+5 .. r4+18
            const float* base = sh11 + (r4 + 5) * 32 + oc2;
            ull w0=0, w1=0, w2=0, w3=0;
            #pragma unroll
            for (int i = 0; i < 14; i++) {
                w3 = w2; w2 = w1; w1 = w0;
                if (i <= 10) w0 = wd11[i];
                const ull v = *(const ull*)(base + i * 32);
                if (i <= 10)           vacc[0] = fma2(w0, v, vacc[0]);
                if (i >= 1 && i <= 11) vacc[1] = fma2(w1, v, vacc[1]);
                if (i >= 2 && i <= 12) vacc[2] = fma2(w2, v, vacc[2]);
                if (i >= 3)            vacc[3] = fma2(w3, v, vacc[3]);
            }
        }
        {   // v7: sh7 rows r4+7 .. r4+16
            const float* base = sh7 + (r4 + 7) * 32 + oc2;
            ull w0=0, w1=0, w2=0, w3=0;
            #pragma unroll
            for (int i = 0; i < 10; i++) {
                w3 = w2; w2 = w1; w1 = w0;
                if (i <= 6) w0 = wd7[i];
                const ull v = *(const ull*)(base + i * 32);
                if (i <= 6)           vacc[0] = fma2(w0, v, vacc[0]);
                if (i >= 1 && i <= 7) vacc[1] = fma2(w1, v, vacc[1]);
                if (i >= 2 && i <= 8) vacc[2] = fma2(w2, v, vacc[2]);
                if (i >= 3)           vacc[3] = fma2(w3, v, vacc[3]);
            }
        }

        #pragma unroll
        for (int t = 0; t < 4; t++) {
            const float2 vr = unpack2(vacc[t]);
            float2 o;
            o.x = vr.x + sacc[t][0];
            o.y = vr.y + sacc[t][1];
            *(float2*)&Tp[(r4 + t) * NW + oc2] = o;
        }
    }
}

// ---------------------------------------------------------------------------
// Kernel B: out = (W[64x64] @ T + 3*b11) * x, packed f32x2.
// Block: 64 out-channels x 128 pixels. Thread: 8 och x 2 pixel-pairs.
// ---------------------------------------------------------------------------
#define SMEM_B_FLOATS (8192 + 8192 + 128)

__global__ __launch_bounds__(256, 3) void msca_pw_kernel(
    const float* __restrict__ x,
    const float* __restrict__ w11, const float* __restrict__ b11,
    float* __restrict__ out)
{
    extern __shared__ float sm[];
    float*  sT  = sm;                       // [64][128]
    float2* sWd = (float2*)(sm + 8192);     // [64][64] dup'd weights
    float2* sBd = (float2*)(sm + 16384);    // [64] dup'd 3*bias

    const int b   = blockIdx.y;
    const int p0  = blockIdx.x * 128;
    const int tid = threadIdx.x;

    const float* Tb = g_T + (size_t)b * (NC * NPIX) + p0;
    #pragma unroll
    for (int k = 0; k < 8; k++) {
        const int idx = tid + k * 256;            // 2048 float4s
        const int row = idx >> 5, j4 = idx & 31;
        ((float4*)sT)[idx] = *(const float4*)(Tb + (size_t)row * NPIX + j4 * 4);
    }
    #pragma unroll
    for (int k = 0; k < 16; k++) {
        const int idx = tid + k * 256;            // 4096 weights
        const float w = w11[idx];
        sWd[idx] = make_float2(w, w);
    }
    if (tid < 64) {
        const float w = 3.f * b11[tid];
        sBd[tid] = make_float2(w, w);
    }
    __syncthreads();

    const int pg = tid & 31;   // pixels pg*4 .. pg*4+3 (two packed pairs)
    const int og = tid >> 5;   // out-ch og*8 .. og*8+7

    const ull* sT2 = (const ull*)sT;
    const ull* sW2 = (const ull*)sWd;

    ull acc[8][2];
    #pragma unroll
    for (int i = 0; i < 8; i++) { acc[i][0] = 0ull; acc[i][1] = 0ull; }

    #pragma unroll 8
    for (int k = 0; k < 64; k++) {
        const ull t01 = sT2[k * 64 + pg * 2];
        const ull t23 = sT2[k * 64 + pg * 2 + 1];
        #pragma unroll
        for (int i = 0; i < 8; i++) {
            const ull wd = sW2[(og * 8 + i) * 64 + k];   // warp-uniform broadcast
            acc[i][0] = fma2(wd, t01, acc[i][0]);
            acc[i][1] = fma2(wd, t23, acc[i][1]);
        }
    }

    const float* xb = x + (size_t)b * (NC * NPIX) + p0;
    float*       ob = out + (size_t)b * (NC * NPIX) + p0;
    #pragma unroll
    for (int i = 0; i < 8; i++) {
        const int o = og * 8 + i;
        const ull bd = ((const ull*)sBd)[o];
        const ulonglong2 xv = *(const ulonglong2*)&xb[(size_t)o * NPIX + pg * 4];
        ulonglong2 r;
        r.x = mul2(add2(acc[i][0], bd), xv.x);
        r.y = mul2(add2(acc[i][1], bd), xv.y);
        *(ulonglong2*)&ob[(size_t)o * NPIX + pg * 4] = r;
    }
}

// ---------------------------------------------------------------------------
extern "C" void kernel_launch(void* const* d_in, const int* in_sizes, int n_in,
                              void* d_out, int out_size)
{
    const float* x      = (const float*)d_in[0];
    const float* w55    = (const float*)d_in[1];
    const float* b55    = (const float*)d_in[2];
    const float* w17_0  = (const float*)d_in[3];
    const float* b17_0  = (const float*)d_in[4];
    const float* w17_1  = (const float*)d_in[5];
    const float* b17_1  = (const float*)d_in[6];
    const float* w111_0 = (const float*)d_in[7];
    const float* b111_0 = (const float*)d_in[8];
    const float* w111_1 = (const float*)d_in[9];
    const float* b111_1 = (const float*)d_in[10];
    const float* w211_0 = (const float*)d_in[11];
    const float* b211_0 = (const float*)d_in[12];
    const float* w211_1 = (const float*)d_in[13];
    const float* b211_1 = (const float*)d_in[14];
    const float* w11    = (const float*)d_in[15];
    const float* b11    = (const float*)d_in[16];
    float* out = (float*)d_out;

    const int smemA = SMEM_A_FLOATS * sizeof(float);   // 109,928 B
    const int smemB = SMEM_B_FLOATS * sizeof(float);   // 66,048 B

    cudaFuncSetAttribute(msca_dw_kernel, cudaFuncAttributeMaxDynamicSharedMemorySize, smemA);
    cudaFuncSetAttribute(msca_pw_kernel, cudaFuncAttributeMaxDynamicSharedMemorySize, smemB);

    dim3 gA(NW / TW, NC, NB);
    msca_dw_kernel<<<gA, 256, smemA>>>(x,
        w55, b55, w17_0, b17_0, w17_1, b17_1,
        w111_0, b111_0, w111_1, b111_1,
        w211_0, b211_0, w211_1, b211_1);

    dim3 gB(NPIX / 128, NB);
    msca_pw_kernel<<<gB, 256, smemB>>>(x, w11, b11, out);
}